// round 1
// baseline (speedup 1.0000x reference)
#include <cuda_runtime.h>
#include <math.h>

// Problem constants (B=4, F=100, n_peaks=16, W=H=64)
#define B_SZ 4
#define F_SZ 100
#define NP 16
#define PIX 4096              // W*H
#define TPB 128
#define FC 25                 // frequencies per CTA chunk
#define NFC (F_SZ / FC)       // 4 chunks

#define FLT_EPS_F 1.1920929e-7f
#define SQRT_2LN_D 4.0786686f       // sqrt(2*ln(4096))
#define LOG_NPEAKS 2.7725887f       // ln(16)

#define MAG_COUNT ((size_t)B_SZ * F_SZ * PIX)            // 1,638,400
#define DIR_OFF   MAG_COUNT
#define AUX_OFF   (MAG_COUNT + 2 * MAG_COUNT)            // 4,915,200

__device__ float g_norm[B_SZ * NP];

// ---------------------------------------------------------------------------
// Kernel 1: norm[b,p] = max(x) + 0.5*log(sum exp(2*(x-max))) over 4096 elems
// ---------------------------------------------------------------------------
__global__ void norm_kernel(const float* __restrict__ shapes) {
    const int bp = blockIdx.x;            // 0..63
    const int b = bp >> 4, p = bp & 15;
    const float* x = shapes + ((size_t)(b * 48 + p)) * PIX;  // component 0
    const int tid = threadIdx.x;
    __shared__ float sh[256];

    float m = -3.4e38f;
    for (int i = tid; i < PIX; i += 256) m = fmaxf(m, x[i]);
    sh[tid] = m; __syncthreads();
    for (int s = 128; s > 0; s >>= 1) {
        if (tid < s) sh[tid] = fmaxf(sh[tid], sh[tid + s]);
        __syncthreads();
    }
    m = sh[0]; __syncthreads();

    float acc = 0.f;
    for (int i = tid; i < PIX; i += 256) acc += __expf(2.0f * (x[i] - m));
    sh[tid] = acc; __syncthreads();
    for (int s = 128; s > 0; s >>= 1) {
        if (tid < s) sh[tid] += sh[tid + s];
        __syncthreads();
    }
    if (tid == 0) g_norm[bp] = m + 0.5f * logf(sh[0]);
}

// ---------------------------------------------------------------------------
// Kernel 2: aux_sparse = mean over (b,p) of softplus(0.5*logsumexp_f(2*c))
// ---------------------------------------------------------------------------
__global__ void aux_kernel(const float* __restrict__ resp, float* __restrict__ out_aux) {
    const int tid = threadIdx.x;          // 64 threads
    const int b = tid >> 4, p = tid & 15;
    float m = -3.4e38f;
    for (int f = 0; f < F_SZ; f++)
        m = fmaxf(m, resp[((size_t)b * F_SZ + f) * 48 + p]);
    float s = 0.f;
    for (int f = 0; f < F_SZ; f++) {
        float v = resp[((size_t)b * F_SZ + f) * 48 + p];
        s += __expf(2.0f * (v - m));
    }
    float c = m + 0.5f * logf(s);
    float sp = fmaxf(c, 0.0f) + log1pf(__expf(-fabsf(c)));  // stable softplus

    __shared__ float sh[64];
    sh[tid] = sp; __syncthreads();
    for (int st = 32; st > 0; st >>= 1) {
        if (tid < st) sh[tid] += sh[tid + st];
        __syncthreads();
    }
    if (tid == 0) *out_aux = sh[0] * (1.0f / 64.0f);
}

// ---------------------------------------------------------------------------
// Kernel 3: main field. One thread per pixel; shape data (16 peaks x 3) in
// registers; per-f responses + bias in smem; loop over FC frequencies.
// ---------------------------------------------------------------------------
__global__ __launch_bounds__(TPB) void field_kernel(
    const float* __restrict__ shapes,
    const float* __restrict__ resp,
    const float* __restrict__ freqs,
    float* __restrict__ out)
{
    const int b   = blockIdx.y;
    const int fc  = blockIdx.z;
    const int pix = blockIdx.x * TPB + threadIdx.x;
    const int tid = threadIdx.x;

    __shared__ float s_r0[FC][NP];
    __shared__ float s_tr[FC][NP];
    __shared__ float s_ti[FC][NP];
    __shared__ float s_bias[FC];

    // Load response chunk: magnitude offset + normalized t direction
    for (int idx = tid; idx < FC * NP; idx += TPB) {
        int lf = idx >> 4, p = idx & 15;
        int f = fc * FC + lf;
        size_t rb = ((size_t)b * F_SZ + f) * 48;
        s_r0[lf][p] = resp[rb + p];
        float tr = resp[rb + 16 + p], ti = resp[rb + 32 + p];
        float inv = rsqrtf(fmaxf(tr * tr + ti * ti, FLT_EPS_F));
        s_tr[lf][p] = tr * inv;
        s_ti[lf][p] = ti * inv;
    }
    // Frequency bias (interp of cos table), pre-halved
    if (tid < FC) {
        float fq = freqs[b * F_SZ + fc * FC + tid];
        float pos = fminf(fmaxf((fq + 1.0f) * 0.5f * 127.0f, 0.0f), 127.0f);
        float lof = floorf(pos);
        int lo = (int)lof;
        int hi = min(lo + 1, 127);
        float w = pos - lof;
        const float k = 3.14159265358979323846f / 127.0f;
        float Tlo = cosf((float)lo * k) * 1.5f - 3.0f;
        float Thi = cosf((float)hi * k) * 1.5f - 3.0f;
        s_bias[tid] = 0.5f * (Tlo * (1.0f - w) + Thi * w);
    }
    __syncthreads();

    // Per-pixel shape registers: ms_ln and normalized spatial direction
    float ms[NP], xr[NP], xi[NP];
    const float* sb = shapes + (size_t)b * 3 * NP * PIX + pix;
    #pragma unroll
    for (int p = 0; p < NP; p++) {
        float a  = sb[p * PIX];
        ms[p] = a - g_norm[b * NP + p] + SQRT_2LN_D;
        float r  = sb[NP * PIX + p * PIX];
        float im = sb[2 * NP * PIX + p * PIX];
        float inv = rsqrtf(fmaxf(r * r + im * im, FLT_EPS_F));
        xr[p] = r * inv;
        xi[p] = im * inv;
    }

    for (int lf = 0; lf < FC; lf++) {
        float mag[NP];
        float m = -3.4e38f;
        #pragma unroll
        for (int p = 0; p < NP; p++) {
            mag[p] = ms[p] + s_r0[lf][p];
            m = fmaxf(m, mag[p]);
        }
        float sr = 0.f, si = 0.f;
        #pragma unroll
        for (int p = 0; p < NP; p++) {
            float w  = __expf(mag[p] - m);
            float wr = w * xr[p];
            float wi = w * xi[p];
            float tr = s_tr[lf][p];
            float ti = s_ti[lf][p];
            sr = fmaf(wr, tr, sr); sr = fmaf(-wi, ti, sr);
            si = fmaf(wr, ti, si); si = fmaf(wi, tr, si);
        }
        float ss  = fmaf(sr, sr, fmaf(si, si, 0.001f));
        float inv = rsqrtf(ss);
        float ln  = m + 0.5f * __logf(ss);

        int f = fc * FC + lf;
        size_t o = ((size_t)b * F_SZ + f) * PIX + pix;
        out[o] = ln - LOG_NPEAKS + s_bias[lf];
        size_t d0 = DIR_OFF + (((size_t)b * F_SZ + f) * 2) * PIX + pix;
        out[d0]       = sr * inv;
        out[d0 + PIX] = si * inv;
    }
}

extern "C" void kernel_launch(void* const* d_in, const int* in_sizes, int n_in,
                              void* d_out, int out_size) {
    const float* shapes = (const float*)d_in[0];  // (4,3,16,64,64)
    const float* resp   = (const float*)d_in[1];  // (4,100,3,16)
    const float* freqs  = (const float*)d_in[2];  // (4,100)
    float* out = (float*)d_out;

    norm_kernel<<<B_SZ * NP, 256>>>(shapes);
    aux_kernel<<<1, 64>>>(resp, out + AUX_OFF);
    dim3 grid(PIX / TPB, B_SZ, NFC);
    field_kernel<<<grid, TPB>>>(shapes, resp, freqs, out);
}

// round 3
// speedup vs baseline: 1.5882x; 1.5882x over previous
#include <cuda_runtime.h>
#include <math.h>

// Problem constants (B=4, F=100, n_peaks=16, W=H=64)
#define B_SZ 4
#define F_SZ 100
#define NP 16
#define PIX 4096
#define TPB 128
#define FC 25
#define NFC (F_SZ / FC)

#define FLT_EPS_F 1.1920929e-7f
#define SQRT_2LN_D 4.0786686f       // sqrt(2*ln(4096))
#define LOG_NPEAKS 2.7725887f       // ln(16)

#define MAG_COUNT ((size_t)B_SZ * F_SZ * PIX)   // 1,638,400
#define DIR_OFF   MAG_COUNT
#define AUX_OFF   (3 * MAG_COUNT)               // 4,915,200

#define NROWS (B_SZ * F_SZ)                     // 400

__device__ float  g_part[256];                  // per-(b,p) quarter sums of exp(2x)
__device__ float4 g_c[NROWS * NP];              // {Er0, Er0*tr_hat, Er0*ti_hat, 0}
__device__ float  g_bias[NROWS];                // pre-halved interp bias

// ---------------------------------------------------------------------------
// Kernel 1: fused prep
//   blocks [0,256):   norm partial sums  (bp = blk>>2, quarter = blk&3)
//   blocks [256,264): response precompute + bias
//   block  264:       aux_sparse
// ---------------------------------------------------------------------------
__global__ __launch_bounds__(256) void prep_kernel(
    const float* __restrict__ shapes,
    const float* __restrict__ resp,
    const float* __restrict__ freqs,
    float* __restrict__ out_aux)
{
    const int blk = blockIdx.x;
    const int tid = threadIdx.x;
    __shared__ float sh[256];

    if (blk < 256) {
        // ---- norm partials: sum exp(2x) over 1024 elems (float4 loads) ----
        const int bp = blk >> 2, q = blk & 3;
        const int b = bp >> 4, p = bp & 15;
        const float4* x = (const float4*)(shapes + ((size_t)(b * 48 + p)) * PIX + q * 1024);
        float4 v = x[tid];
        float s = __expf(2.f * v.x) + __expf(2.f * v.y)
                + __expf(2.f * v.z) + __expf(2.f * v.w);
        sh[tid] = s; __syncthreads();
        #pragma unroll
        for (int st = 128; st > 32; st >>= 1) {
            if (tid < st) sh[tid] += sh[tid + st];
            __syncthreads();
        }
        if (tid < 32) {
            float v2 = sh[tid] + sh[tid + 32];
            #pragma unroll
            for (int o = 16; o > 0; o >>= 1)
                v2 += __shfl_down_sync(0xffffffff, v2, o);
            if (tid == 0) g_part[blk] = v2;
        }
    } else if (blk < 264) {
        // ---- response precompute: 6400 items, 2048 threads ----
        for (int idx = (blk - 256) * 256 + tid; idx < NROWS * NP; idx += 8 * 256) {
            const int row = idx >> 4, p = idx & 15;
            const float* rb = resp + (size_t)row * 48;
            float er = __expf(rb[p]);
            float tr = rb[16 + p], ti = rb[32 + p];
            float inv = rsqrtf(fmaxf(tr * tr + ti * ti, FLT_EPS_F));
            g_c[idx] = make_float4(er, er * tr * inv, er * ti * inv, 0.f);
            if (p == 0) {
                float fq  = freqs[row];
                float pos = fminf(fmaxf((fq + 1.0f) * 0.5f * 127.0f, 0.0f), 127.0f);
                float lof = floorf(pos);
                int   lo  = (int)lof;
                int   hi  = min(lo + 1, 127);
                float w   = pos - lof;
                const float k = 3.14159265358979323846f / 127.0f;
                float Tlo = cosf((float)lo * k) * 1.5f - 3.0f;
                float Thi = cosf((float)hi * k) * 1.5f - 3.0f;
                g_bias[row] = 0.5f * (Tlo * (1.0f - w) + Thi * w);
            }
        }
    } else {
        // ---- aux_sparse: 4 threads per (b,p), 25 f's each ----
        const int bp = tid & 63, g = tid >> 6;
        const int b = bp >> 4, p = bp & 15;
        float s = 0.f;
        for (int f = g * 25; f < g * 25 + 25; f++)
            s += __expf(2.0f * resp[((size_t)b * F_SZ + f) * 48 + p]);
        sh[tid] = s; __syncthreads();
        if (tid < 64) {
            float st = sh[tid] + sh[tid + 64] + sh[tid + 128] + sh[tid + 192];
            float c  = 0.5f * logf(st);
            sh[tid]  = fmaxf(c, 0.0f) + log1pf(__expf(-fabsf(c)));
        }
        __syncthreads();
        if (tid < 32) {
            float v = sh[tid] + sh[tid + 32];
            #pragma unroll
            for (int o = 16; o > 0; o >>= 1)
                v += __shfl_down_sync(0xffffffff, v, o);
            if (tid == 0) *out_aux = v * (1.0f / 64.0f);
        }
    }
}

// ---------------------------------------------------------------------------
// Kernel 2: main field. No exp/max in the inner loop — exact max-shift is
// recovered as wm = max_p(E_p * Er0_p), so eps semantics match the reference.
// ---------------------------------------------------------------------------
__global__ __launch_bounds__(TPB) void field_kernel(
    const float* __restrict__ shapes,
    float* __restrict__ out)
{
    const int b   = blockIdx.y;
    const int fc  = blockIdx.z;
    const int pix = blockIdx.x * TPB + threadIdx.x;
    const int tid = threadIdx.x;

    __shared__ float4 sc[FC][NP];
    __shared__ float  sbias[FC];

    const int row0 = b * F_SZ + fc * FC;
    for (int i = tid; i < FC * NP; i += TPB)
        sc[i >> 4][i & 15] = g_c[row0 * NP + i];
    if (tid < FC) sbias[tid] = g_bias[row0 + tid];

    // Per-pixel setup: E = exp(a + sqrt(2 ln d)) / sqrt(sum exp(2x)),
    // Exr/Exi = E * normalized spatial direction.
    float E[NP], Exr[NP], Exi[NP];
    const float* sb = shapes + (size_t)b * 3 * NP * PIX + pix;
    #pragma unroll
    for (int p = 0; p < NP; p++) {
        const int g4 = (b * NP + p) * 4;
        float S = g_part[g4] + g_part[g4 + 1] + g_part[g4 + 2] + g_part[g4 + 3];
        float a = sb[p * PIX];
        float e = __expf(a + SQRT_2LN_D) * rsqrtf(S);
        float r  = sb[(NP + p) * PIX];
        float im = sb[(2 * NP + p) * PIX];
        float inv = rsqrtf(fmaxf(r * r + im * im, FLT_EPS_F));
        E[p]   = e;
        Exr[p] = e * r * inv;
        Exi[p] = e * im * inv;
    }
    __syncthreads();

    for (int lf = 0; lf < FC; lf++) {
        float sr = 0.f, si = 0.f, wm = 0.f;
        #pragma unroll
        for (int p = 0; p < NP; p++) {
            float4 c = sc[lf][p];
            float w = E[p] * c.x;
            wm = fmaxf(wm, w);
            sr = fmaf(Exr[p],  c.y, sr);
            sr = fmaf(-Exi[p], c.z, sr);
            si = fmaf(Exr[p],  c.z, si);
            si = fmaf(Exi[p],  c.y, si);
        }
        // ss = e^{2m} * (sr_shift^2 + si_shift^2 + eps)  with m = max_p mag
        float ss  = fmaf(sr, sr, fmaf(si, si, 0.001f * wm * wm));
        float inv = rsqrtf(ss);
        float ln  = 0.5f * __logf(ss);

        const int f = fc * FC + lf;
        const size_t o  = ((size_t)b * F_SZ + f) * PIX + pix;
        out[o] = ln - LOG_NPEAKS + sbias[lf];
        const size_t d0 = DIR_OFF + (((size_t)b * F_SZ + f) * 2) * PIX + pix;
        out[d0]       = sr * inv;
        out[d0 + PIX] = si * inv;
    }
}

extern "C" void kernel_launch(void* const* d_in, const int* in_sizes, int n_in,
                              void* d_out, int out_size) {
    const float* shapes = (const float*)d_in[0];  // (4,3,16,64,64)
    const float* resp   = (const float*)d_in[1];  // (4,100,3,16)
    const float* freqs  = (const float*)d_in[2];  // (4,100)
    float* out = (float*)d_out;

    prep_kernel<<<265, 256>>>(shapes, resp, freqs, out + AUX_OFF);
    dim3 grid(PIX / TPB, B_SZ, NFC);
    field_kernel<<<grid, TPB>>>(shapes, out);
}

// round 4
// speedup vs baseline: 1.5981x; 1.0062x over previous
#include <cuda_runtime.h>
#include <math.h>

// Problem constants (B=4, F=100, n_peaks=16, W=H=64)
#define B_SZ 4
#define F_SZ 100
#define NP 16
#define PIX 4096
#define TPB 128
#define FC 10
#define NFC (F_SZ / FC)

#define FLT_EPS_F 1.1920929e-7f
#define SQRT_2LN_D 4.0786686f       // sqrt(2*ln(4096))
#define EXP_S2LD   59.066666f       // exp(SQRT_2LN_D)
#define LOG_NPEAKS 2.7725887f       // ln(16)

#define MAG_COUNT ((size_t)B_SZ * F_SZ * PIX)   // 1,638,400
#define DIR_OFF   MAG_COUNT
#define AUX_OFF   (3 * MAG_COUNT)               // 4,915,200

#define NROWS (B_SZ * F_SZ)                     // 400

__device__ float  g_part[256];                  // per-(b,p) quarter sums of exp(2x)
__device__ float4 g_c[NROWS * NP];              // {Er0, Er0*tr_hat, Er0*ti_hat, 0}
__device__ float  g_bias[NROWS];                // pre-halved interp bias

// ---------------------------------------------------------------------------
// Kernel 1: fused prep
//   blocks [0,256):   norm partial sums  (bp = blk>>2, quarter = blk&3)
//   blocks [256,264): response precompute + bias
//   block  264:       aux_sparse
// ---------------------------------------------------------------------------
__global__ __launch_bounds__(256) void prep_kernel(
    const float* __restrict__ shapes,
    const float* __restrict__ resp,
    const float* __restrict__ freqs,
    float* __restrict__ out_aux)
{
    const int blk = blockIdx.x;
    const int tid = threadIdx.x;
    __shared__ float sh[256];

    if (blk < 256) {
        // ---- norm partials: sum exp(2x) over 1024 elems (float4 loads) ----
        const int bp = blk >> 2, q = blk & 3;
        const int b = bp >> 4, p = bp & 15;
        const float4* x = (const float4*)(shapes + ((size_t)(b * 48 + p)) * PIX + q * 1024);
        float4 v = x[tid];
        float s = __expf(2.f * v.x) + __expf(2.f * v.y)
                + __expf(2.f * v.z) + __expf(2.f * v.w);
        sh[tid] = s; __syncthreads();
        #pragma unroll
        for (int st = 128; st > 32; st >>= 1) {
            if (tid < st) sh[tid] += sh[tid + st];
            __syncthreads();
        }
        if (tid < 32) {
            float v2 = sh[tid] + sh[tid + 32];
            #pragma unroll
            for (int o = 16; o > 0; o >>= 1)
                v2 += __shfl_down_sync(0xffffffff, v2, o);
            if (tid == 0) g_part[blk] = v2;
        }
    } else if (blk < 264) {
        // ---- response precompute: 6400 items, 2048 threads ----
        for (int idx = (blk - 256) * 256 + tid; idx < NROWS * NP; idx += 8 * 256) {
            const int row = idx >> 4, p = idx & 15;
            const float* rb = resp + (size_t)row * 48;
            float er = __expf(rb[p]);
            float tr = rb[16 + p], ti = rb[32 + p];
            float inv = rsqrtf(fmaxf(tr * tr + ti * ti, FLT_EPS_F));
            g_c[idx] = make_float4(er, er * tr * inv, er * ti * inv, 0.f);
            if (p == 0) {
                float fq  = freqs[row];
                float pos = fminf(fmaxf((fq + 1.0f) * 0.5f * 127.0f, 0.0f), 127.0f);
                float lof = floorf(pos);
                int   lo  = (int)lof;
                int   hi  = min(lo + 1, 127);
                float w   = pos - lof;
                const float k = 3.14159265358979323846f / 127.0f;
                float Tlo = cosf((float)lo * k) * 1.5f - 3.0f;
                float Thi = cosf((float)hi * k) * 1.5f - 3.0f;
                g_bias[row] = 0.5f * (Tlo * (1.0f - w) + Thi * w);
            }
        }
    } else {
        // ---- aux_sparse: 4 threads per (b,p), 25 f's each ----
        const int bp = tid & 63, g = tid >> 6;
        const int b = bp >> 4, p = bp & 15;
        float s = 0.f;
        for (int f = g * 25; f < g * 25 + 25; f++)
            s += __expf(2.0f * resp[((size_t)b * F_SZ + f) * 48 + p]);
        sh[tid] = s; __syncthreads();
        if (tid < 64) {
            float st = sh[tid] + sh[tid + 64] + sh[tid + 128] + sh[tid + 192];
            float c  = 0.5f * logf(st);
            sh[tid]  = fmaxf(c, 0.0f) + log1pf(__expf(-fabsf(c)));
        }
        __syncthreads();
        if (tid < 32) {
            float v = sh[tid] + sh[tid + 32];
            #pragma unroll
            for (int o = 16; o > 0; o >>= 1)
                v += __shfl_down_sync(0xffffffff, v, o);
            if (tid == 0) *out_aux = v * (1.0f / 64.0f);
        }
    }
}

// ---------------------------------------------------------------------------
// Kernel 2: main field. No exp/max in the inner loop — exact max-shift is
// recovered as wm = max_p(E_p * Er0_p), so eps semantics match the reference.
// ---------------------------------------------------------------------------
__global__ __launch_bounds__(TPB, 7) void field_kernel(
    const float* __restrict__ shapes,
    float* __restrict__ out)
{
    const int b   = blockIdx.y;
    const int fc  = blockIdx.z;
    const int pix = blockIdx.x * TPB + threadIdx.x;
    const int tid = threadIdx.x;

    __shared__ float4 sc[FC][NP];
    __shared__ float  sbias[FC];
    __shared__ float  sinvs[NP];    // exp(sqrt(2 ln d)) / sqrt(S[b][p])

    const int row0 = b * F_SZ + fc * FC;
    for (int i = tid; i < FC * NP; i += TPB)
        sc[i >> 4][i & 15] = g_c[row0 * NP + i];
    if (tid < FC) sbias[tid] = g_bias[row0 + tid];
    if (tid >= 32 && tid < 32 + NP) {
        const int p = tid - 32;
        const int g4 = (b * NP + p) * 4;
        float S = g_part[g4] + g_part[g4 + 1] + g_part[g4 + 2] + g_part[g4 + 3];
        sinvs[p] = EXP_S2LD * rsqrtf(S);
    }
    __syncthreads();

    // Per-pixel setup: E = exp(a)*invs, Exr/Exi = E * normalized spatial dir
    float E[NP], Exr[NP], Exi[NP];
    const float* sb = shapes + (size_t)b * 3 * NP * PIX + pix;
    #pragma unroll
    for (int p = 0; p < NP; p++) {
        float a  = sb[p * PIX];
        float e  = __expf(a) * sinvs[p];
        float r  = sb[(NP + p) * PIX];
        float im = sb[(2 * NP + p) * PIX];
        float inv = rsqrtf(fmaxf(r * r + im * im, FLT_EPS_F));
        E[p]   = e;
        Exr[p] = e * r * inv;
        Exi[p] = e * im * inv;
    }

    float*       magp = out + (size_t)row0 * PIX + pix;
    float*       dirp = out + DIR_OFF + (size_t)row0 * 2 * PIX + pix;

    #pragma unroll 2
    for (int lf = 0; lf < FC; lf++) {
        float sr0 = 0.f, sr1 = 0.f, si0 = 0.f, si1 = 0.f, wm = 0.f;
        #pragma unroll
        for (int p = 0; p < NP; p += 2) {
            float4 c0 = sc[lf][p];
            float4 c1 = sc[lf][p + 1];
            wm  = fmaxf(wm, E[p] * c0.x);
            sr0 = fmaf(Exr[p],      c0.y, sr0); sr0 = fmaf(-Exi[p],     c0.z, sr0);
            si0 = fmaf(Exr[p],      c0.z, si0); si0 = fmaf(Exi[p],      c0.y, si0);
            wm  = fmaxf(wm, E[p + 1] * c1.x);
            sr1 = fmaf(Exr[p + 1],  c1.y, sr1); sr1 = fmaf(-Exi[p + 1], c1.z, sr1);
            si1 = fmaf(Exr[p + 1],  c1.z, si1); si1 = fmaf(Exi[p + 1],  c1.y, si1);
        }
        float sr = sr0 + sr1, si = si0 + si1;
        // ss = e^{2m} * (sr_shift^2 + si_shift^2 + eps)  with m = max_p mag
        float ss  = fmaf(sr, sr, fmaf(si, si, 0.001f * wm * wm));
        float inv = rsqrtf(ss);
        float ln  = 0.5f * __logf(ss);

        magp[lf * PIX]           = ln - LOG_NPEAKS + sbias[lf];
        dirp[lf * 2 * PIX]       = sr * inv;
        dirp[lf * 2 * PIX + PIX] = si * inv;
    }
}

extern "C" void kernel_launch(void* const* d_in, const int* in_sizes, int n_in,
                              void* d_out, int out_size) {
    const float* shapes = (const float*)d_in[0];  // (4,3,16,64,64)
    const float* resp   = (const float*)d_in[1];  // (4,100,3,16)
    const float* freqs  = (const float*)d_in[2];  // (4,100)
    float* out = (float*)d_out;

    prep_kernel<<<265, 256>>>(shapes, resp, freqs, out + AUX_OFF);
    dim3 grid(PIX / TPB, B_SZ, NFC);
    field_kernel<<<grid, TPB>>>(shapes, out);
}

// round 5
// speedup vs baseline: 1.6820x; 1.0525x over previous
#include <cuda_runtime.h>
#include <math.h>

// Problem constants (B=4, F=100, n_peaks=16, W=H=64)
#define B_SZ 4
#define F_SZ 100
#define NP 16
#define PIX 4096
#define TPB 128
#define NFC 8                 // 8 chunks: 4x13 + 4x12 = 100  -> 1024 CTAs = one wave @ occ 7
#define FCMAX 13

#define FLT_EPS_F 1.1920929e-7f
#define SQRT_2LN_D 4.0786686f       // sqrt(2*ln(4096))
#define EXP_S2LD   59.066666f       // exp(SQRT_2LN_D)
#define LOG_NPEAKS 2.7725887f       // ln(16)

#define MAG_COUNT ((size_t)B_SZ * F_SZ * PIX)   // 1,638,400
#define DIR_OFF   MAG_COUNT
#define AUX_OFF   (3 * MAG_COUNT)               // 4,915,200

#define NROWS (B_SZ * F_SZ)                     // 400

__device__ float  g_part[256];                  // per-(b,p) quarter sums of exp(2x)
__device__ float4 g_c[NROWS * NP];              // {Er0, Er0*tr_hat, Er0*ti_hat, 0}
__device__ float  g_bias[NROWS];                // pre-halved interp bias

// ---------------------------------------------------------------------------
// Kernel 1: fused prep
// ---------------------------------------------------------------------------
__global__ __launch_bounds__(256) void prep_kernel(
    const float* __restrict__ shapes,
    const float* __restrict__ resp,
    const float* __restrict__ freqs,
    float* __restrict__ out_aux)
{
    const int blk = blockIdx.x;
    const int tid = threadIdx.x;
    __shared__ float sh[256];

    if (blk < 256) {
        // ---- norm partials: sum exp(2x) over 1024 elems (float4 loads) ----
        const int bp = blk >> 2, q = blk & 3;
        const int b = bp >> 4, p = bp & 15;
        const float4* x = (const float4*)(shapes + ((size_t)(b * 48 + p)) * PIX + q * 1024);
        float4 v = x[tid];
        float s = __expf(2.f * v.x) + __expf(2.f * v.y)
                + __expf(2.f * v.z) + __expf(2.f * v.w);
        sh[tid] = s; __syncthreads();
        #pragma unroll
        for (int st = 128; st > 32; st >>= 1) {
            if (tid < st) sh[tid] += sh[tid + st];
            __syncthreads();
        }
        if (tid < 32) {
            float v2 = sh[tid] + sh[tid + 32];
            #pragma unroll
            for (int o = 16; o > 0; o >>= 1)
                v2 += __shfl_down_sync(0xffffffff, v2, o);
            if (tid == 0) g_part[blk] = v2;
        }
    } else if (blk < 264) {
        // ---- response precompute: 6400 items ----
        for (int idx = (blk - 256) * 256 + tid; idx < NROWS * NP; idx += 8 * 256) {
            const int row = idx >> 4, p = idx & 15;
            const float* rb = resp + (size_t)row * 48;
            float er = __expf(rb[p]);
            float tr = rb[16 + p], ti = rb[32 + p];
            float inv = rsqrtf(fmaxf(tr * tr + ti * ti, FLT_EPS_F));
            g_c[idx] = make_float4(er, er * tr * inv, er * ti * inv, 0.f);
            if (p == 0) {
                float fq  = freqs[row];
                float pos = fminf(fmaxf((fq + 1.0f) * 0.5f * 127.0f, 0.0f), 127.0f);
                float lof = floorf(pos);
                int   lo  = (int)lof;
                int   hi  = min(lo + 1, 127);
                float w   = pos - lof;
                const float k = 3.14159265358979323846f / 127.0f;
                float Tlo = cosf((float)lo * k) * 1.5f - 3.0f;
                float Thi = cosf((float)hi * k) * 1.5f - 3.0f;
                g_bias[row] = 0.5f * (Tlo * (1.0f - w) + Thi * w);
            }
        }
    } else {
        // ---- aux_sparse ----
        const int bp = tid & 63, g = tid >> 6;
        const int b = bp >> 4, p = bp & 15;
        float s = 0.f;
        for (int f = g * 25; f < g * 25 + 25; f++)
            s += __expf(2.0f * resp[((size_t)b * F_SZ + f) * 48 + p]);
        sh[tid] = s; __syncthreads();
        if (tid < 64) {
            float st = sh[tid] + sh[tid + 64] + sh[tid + 128] + sh[tid + 192];
            float c  = 0.5f * logf(st);
            sh[tid]  = fmaxf(c, 0.0f) + log1pf(__expf(-fabsf(c)));
        }
        __syncthreads();
        if (tid < 32) {
            float v = sh[tid] + sh[tid + 32];
            #pragma unroll
            for (int o = 16; o > 0; o >>= 1)
                v += __shfl_down_sync(0xffffffff, v, o);
            if (tid == 0) *out_aux = v * (1.0f / 64.0f);
        }
    }
}

// ---------------------------------------------------------------------------
// Kernel 2: main field. Single full wave: 1024 CTAs @ 7/SM.
// ---------------------------------------------------------------------------
__global__ __launch_bounds__(TPB, 7) void field_kernel(
    const float* __restrict__ shapes,
    float* __restrict__ out)
{
    const int b   = blockIdx.y;
    const int fc  = blockIdx.z;
    const int pix = blockIdx.x * TPB + threadIdx.x;
    const int tid = threadIdx.x;

    // chunk boundaries: first 4 chunks have 13 freqs, last 4 have 12
    const int f0  = fc * 12 + min(fc, 4);
    const int len = (fc < 4) ? 13 : 12;

    __shared__ float4 sc[FCMAX][NP];
    __shared__ float  sbias[FCMAX];
    __shared__ float  sinvs[NP];

    const int row0 = b * F_SZ + f0;
    for (int i = tid; i < len * NP; i += TPB)
        sc[i >> 4][i & 15] = g_c[row0 * NP + i];
    if (tid < len) sbias[tid] = g_bias[row0 + tid];
    if (tid >= 32 && tid < 32 + NP) {
        const int p = tid - 32;
        const int g4 = (b * NP + p) * 4;
        float S = g_part[g4] + g_part[g4 + 1] + g_part[g4 + 2] + g_part[g4 + 3];
        sinvs[p] = EXP_S2LD * rsqrtf(S);
    }
    __syncthreads();

    // Per-pixel setup: E = exp(a)*invs, Exr/Exi = E * normalized spatial dir
    float E[NP], Exr[NP], Exi[NP];
    const float* sb = shapes + (size_t)b * 3 * NP * PIX + pix;
    #pragma unroll
    for (int p = 0; p < NP; p++) {
        float a  = sb[p * PIX];
        float e  = __expf(a) * sinvs[p];
        float r  = sb[(NP + p) * PIX];
        float im = sb[(2 * NP + p) * PIX];
        float inv = rsqrtf(fmaxf(r * r + im * im, FLT_EPS_F));
        E[p]   = e;
        Exr[p] = e * r * inv;
        Exi[p] = e * im * inv;
    }

    float* magp = out + (size_t)row0 * PIX + pix;
    float* dirp = out + DIR_OFF + (size_t)row0 * 2 * PIX + pix;

    #pragma unroll 2
    for (int lf = 0; lf < len; lf++) {
        float sr0 = 0.f, sr1 = 0.f, si0 = 0.f, si1 = 0.f, wm = 0.f;
        #pragma unroll
        for (int p = 0; p < NP; p += 2) {
            float4 c0 = sc[lf][p];
            float4 c1 = sc[lf][p + 1];
            wm  = fmaxf(wm, E[p] * c0.x);
            sr0 = fmaf(Exr[p],      c0.y, sr0); sr0 = fmaf(-Exi[p],     c0.z, sr0);
            si0 = fmaf(Exr[p],      c0.z, si0); si0 = fmaf(Exi[p],      c0.y, si0);
            wm  = fmaxf(wm, E[p + 1] * c1.x);
            sr1 = fmaf(Exr[p + 1],  c1.y, sr1); sr1 = fmaf(-Exi[p + 1], c1.z, sr1);
            si1 = fmaf(Exr[p + 1],  c1.z, si1); si1 = fmaf(Exi[p + 1],  c1.y, si1);
        }
        float sr = sr0 + sr1, si = si0 + si1;
        // ss = e^{2m} * (sr_shift^2 + si_shift^2 + eps)  with m = max_p mag
        float ss  = fmaf(sr, sr, fmaf(si, si, 0.001f * wm * wm));
        float inv = rsqrtf(ss);
        float ln  = 0.5f * __logf(ss);

        *magp = ln - LOG_NPEAKS + sbias[lf];
        dirp[0]   = sr * inv;
        dirp[PIX] = si * inv;
        magp += PIX;
        dirp += 2 * PIX;
    }
}

extern "C" void kernel_launch(void* const* d_in, const int* in_sizes, int n_in,
                              void* d_out, int out_size) {
    const float* shapes = (const float*)d_in[0];  // (4,3,16,64,64)
    const float* resp   = (const float*)d_in[1];  // (4,100,3,16)
    const float* freqs  = (const float*)d_in[2];  // (4,100)
    float* out = (float*)d_out;

    prep_kernel<<<265, 256>>>(shapes, resp, freqs, out + AUX_OFF);
    dim3 grid(PIX / TPB, B_SZ, NFC);
    field_kernel<<<grid, TPB>>>(shapes, out);
}